// round 3
// baseline (speedup 1.0000x reference)
#include <cuda_runtime.h>
#include <math.h>

// EnhancedFinancialGAT collapses: initial node features are uniform across all
// N nodes per batch item, so GAT softmax weights (sum to 1 per dst) aggregate
// identical messages -> each layer is relu(W @ g + b), uniform over nodes.
// Whole model = small per-item MLP chain. One block per batch item.
//
// R2 -> R3: kill the latency serialization. 32-reg cap (from min-blocks=8
// launch bounds) limited load MLP to ~4; now give ptxas full register budget,
// fully unroll with compile-time trip counts, 4 accumulators.

#define HIDDEN 256
#define IN_DIM 64
#define EMB_DIM 64
#define FUSE_IN 320

template<int N4>
__device__ __forceinline__ float dotT(const float* __restrict__ w,
                                      const float* __restrict__ v) {
    const float4* __restrict__ w4 = reinterpret_cast<const float4*>(w);
    const float4* __restrict__ v4 = reinterpret_cast<const float4*>(v);
    float a0 = 0.f, a1 = 0.f, a2 = 0.f, a3 = 0.f;
#pragma unroll
    for (int i = 0; i < N4; i++) {
        float4 a = __ldg(&w4[i]);
        float4 b = v4[i];          // warp-uniform smem address -> broadcast
        a0 = fmaf(a.x, b.x, a0);
        a1 = fmaf(a.y, b.y, a1);
        a2 = fmaf(a.z, b.z, a2);
        a3 = fmaf(a.w, b.w, a3);
    }
    return (a0 + a1) + (a2 + a3);
}

__global__ __launch_bounds__(256)
void gat_collapse_kernel(
    const float* __restrict__ x,            // [64,64]
    const int*   __restrict__ company_idx,  // [64]
    const float* __restrict__ W_in,         // [256,64]
    const float* __restrict__ b_in,         // [256]
    const float* __restrict__ gat_W,        // [3,256,256]
    const float* __restrict__ gat_b,        // [3,256]
    const float* __restrict__ emb,          // [2000,64]
    const float* __restrict__ W_fuse,       // [256,320]
    const float* __restrict__ b_fuse,       // [256]
    const float* __restrict__ W_p1, const float* __restrict__ b_p1,  // [128,256]
    const float* __restrict__ W_p2, const float* __restrict__ b_p2,  // [64,128]
    const float* __restrict__ W_p3, const float* __restrict__ b_p3,  // [1,64]
    const float* __restrict__ W_d1, const float* __restrict__ b_d1,
    const float* __restrict__ W_d2, const float* __restrict__ b_d2,
    const float* __restrict__ W_d3, const float* __restrict__ b_d3,
    float* __restrict__ out, int B)
{
    const int b   = blockIdx.x;
    const int tid = threadIdx.x;

    __shared__ __align__(16) float sA[FUSE_IN];   // activations / fuse input
    __shared__ __align__(16) float sB[HIDDEN];
    __shared__ __align__(16) float sC[128];       // p1 out
    __shared__ __align__(16) float sD[128];       // d1 out
    __shared__ __align__(16) float sP2[64];
    __shared__ __align__(16) float sD2[64];

    // 1. load x row
    if (tid < IN_DIM) sA[tid] = x[b * IN_DIM + tid];
    __syncthreads();

    // 2. h = relu(W_in x + b_in) -> sB
    sB[tid] = fmaxf(dotT<IN_DIM / 4>(W_in + tid * IN_DIM, sA) + b_in[tid], 0.f);
    __syncthreads();

    // 3. GAT layers (uniform-node collapse): plain relu(W g + b)
    sA[tid] = fmaxf(dotT<HIDDEN / 4>(gat_W + 0 * HIDDEN * HIDDEN + tid * HIDDEN, sB)
                    + gat_b[0 * HIDDEN + tid], 0.f);
    __syncthreads();
    sB[tid] = fmaxf(dotT<HIDDEN / 4>(gat_W + 1 * HIDDEN * HIDDEN + tid * HIDDEN, sA)
                    + gat_b[1 * HIDDEN + tid], 0.f);
    __syncthreads();
    sA[tid] = fmaxf(dotT<HIDDEN / 4>(gat_W + 2 * HIDDEN * HIDDEN + tid * HIDDEN, sB)
                    + gat_b[2 * HIDDEN + tid], 0.f);
    if (tid < EMB_DIM) {
        int ci = company_idx[b];
        sA[HIDDEN + tid] = emb[ci * EMB_DIM + tid];
    }
    __syncthreads();

    // 4. fused = relu(W_fuse [g; emb] + b_fuse) -> sB
    sB[tid] = fmaxf(dotT<FUSE_IN / 4>(W_fuse + tid * FUSE_IN, sA) + b_fuse[tid], 0.f);
    __syncthreads();

    // 5. p1 (threads 0..127) and d1 (threads 128..255) concurrently
    if (tid < 128) {
        sC[tid] = fmaxf(dotT<HIDDEN / 4>(W_p1 + tid * HIDDEN, sB) + b_p1[tid], 0.f);
    } else {
        int o = tid - 128;
        sD[o] = fmaxf(dotT<HIDDEN / 4>(W_d1 + o * HIDDEN, sB) + b_d1[o], 0.f);
    }
    __syncthreads();

    // 6. p2 (0..63) and d2 (64..127) concurrently
    if (tid < 64) {
        sP2[tid] = fmaxf(dotT<32>(W_p2 + tid * 128, sC) + b_p2[tid], 0.f);
    } else if (tid < 128) {
        int o = tid - 64;
        sD2[o] = fmaxf(dotT<32>(W_d2 + o * 128, sD) + b_d2[o], 0.f);
    }
    __syncthreads();

    // 7. heads
    if (tid == 0) {
        out[b] = dotT<16>(W_p3, sP2) + b_p3[0];                 // price
    } else if (tid == 32) {
        float acc = dotT<16>(W_d3, sD2) + b_d3[0];
        out[64 + b] = 1.f / (1.f + expf(-acc));                 // direction
    }
}

extern "C" void kernel_launch(void* const* d_in, const int* in_sizes, int n_in,
                              void* d_out, int out_size) {
    const float* x        = (const float*)d_in[0];
    const int*   ci       = (const int*)  d_in[1];
    const float* W_in     = (const float*)d_in[4];
    const float* b_in     = (const float*)d_in[5];
    const float* gat_W    = (const float*)d_in[6];
    const float* gat_b    = (const float*)d_in[11];
    const float* emb      = (const float*)d_in[12];
    const float* W_fuse   = (const float*)d_in[13];
    const float* b_fuse   = (const float*)d_in[14];
    const float* W_p1     = (const float*)d_in[15];
    const float* b_p1     = (const float*)d_in[16];
    const float* W_p2     = (const float*)d_in[17];
    const float* b_p2     = (const float*)d_in[18];
    const float* W_p3     = (const float*)d_in[19];
    const float* b_p3     = (const float*)d_in[20];
    const float* W_d1     = (const float*)d_in[21];
    const float* b_d1     = (const float*)d_in[22];
    const float* W_d2     = (const float*)d_in[23];
    const float* b_d2     = (const float*)d_in[24];
    const float* W_d3     = (const float*)d_in[25];
    const float* b_d3     = (const float*)d_in[26];

    const int B = in_sizes[0] / IN_DIM;  // 64

    gat_collapse_kernel<<<B, 256>>>(
        x, ci, W_in, b_in, gat_W, gat_b, emb, W_fuse, b_fuse,
        W_p1, b_p1, W_p2, b_p2, W_p3, b_p3,
        W_d1, b_d1, W_d2, b_d2, W_d3, b_d3,
        (float*)d_out, B);
}

// round 4
// speedup vs baseline: 1.2634x; 1.2634x over previous
#include <cuda_runtime.h>
#include <math.h>

// EnhancedFinancialGAT collapse: initial node features are uniform over all N
// nodes per item, so GAT attention (softmax weights summing to 1) aggregates
// identical messages -> each GAT layer is relu(W @ g + b). Whole net = tiny
// per-item MLP. One block per batch item.
//
// R3 -> R4: grid=64 triggers the low-grid I$ throttle for >32KB bodies, so
// keep code SMALL and hide L2 latency with threads instead of unrolling:
// 1024 thr/block, 4 lanes cooperate per output neuron (qdot + 2-level shfl).

#define HIDDEN 256
#define IN_DIM 64
#define EMB_DIM 64
#define FUSE_IN 320

// 4-lane cooperative dot: lane `sub` (0..3) covers [sub*N/4, (sub+1)*N/4).
// After the xor-butterfly all 4 lanes of the group hold the full sum.
template<int N>
__device__ __forceinline__ float qdot(const float* __restrict__ w,
                                      const float* __restrict__ v, int sub) {
    constexpr int C4 = N / 16;  // float4 per lane
    const float4* __restrict__ w4 = reinterpret_cast<const float4*>(w) + sub * C4;
    const float4* __restrict__ v4 = reinterpret_cast<const float4*>(v) + sub * C4;
    float a0 = 0.f, a1 = 0.f, a2 = 0.f, a3 = 0.f;
#pragma unroll 10
    for (int i = 0; i < C4; i++) {
        float4 a = __ldg(&w4[i]);
        float4 b = v4[i];
        a0 = fmaf(a.x, b.x, a0);
        a1 = fmaf(a.y, b.y, a1);
        a2 = fmaf(a.z, b.z, a2);
        a3 = fmaf(a.w, b.w, a3);
    }
    float r = (a0 + a1) + (a2 + a3);
    r += __shfl_xor_sync(0xffffffffu, r, 1);
    r += __shfl_xor_sync(0xffffffffu, r, 2);
    return r;
}

template<int N>
__device__ __forceinline__ void layer(const float* __restrict__ W,
                                      const float* __restrict__ bias,
                                      const float* __restrict__ vin,
                                      float* __restrict__ vout,
                                      int j, int sub) {
    float r = qdot<N>(W + j * N, vin, sub);
    if (sub == 0) vout[j] = fmaxf(r + bias[j], 0.f);
}

__global__ __launch_bounds__(1024)
void gat_collapse_kernel(
    const float* __restrict__ x,            // [64,64]
    const int*   __restrict__ company_idx,  // [64]
    const float* __restrict__ W_in,         // [256,64]
    const float* __restrict__ b_in,
    const float* __restrict__ gat_W,        // [3,256,256]
    const float* __restrict__ gat_b,        // [3,256]
    const float* __restrict__ emb,          // [2000,64]
    const float* __restrict__ W_fuse,       // [256,320]
    const float* __restrict__ b_fuse,
    const float* __restrict__ W_p1, const float* __restrict__ b_p1,  // [128,256]
    const float* __restrict__ W_p2, const float* __restrict__ b_p2,  // [64,128]
    const float* __restrict__ W_p3, const float* __restrict__ b_p3,  // [1,64]
    const float* __restrict__ W_d1, const float* __restrict__ b_d1,
    const float* __restrict__ W_d2, const float* __restrict__ b_d2,
    const float* __restrict__ W_d3, const float* __restrict__ b_d3,
    float* __restrict__ out, int B)
{
    const int b    = blockIdx.x;
    const int tid  = threadIdx.x;
    const int warp = tid >> 5;
    const int lane = tid & 31;
    const int sub  = tid & 3;
    const int j    = warp * 8 + ((tid >> 2) & 7);   // output index this group owns

    __shared__ __align__(16) float s0[FUSE_IN];
    __shared__ __align__(16) float s1[FUSE_IN];

    // Prefetch: x row into s0[0:64]; emb row straight into s0[256:320]
    // (s0[256:320] is untouched by the intermediate stages).
    if (tid < IN_DIM) {
        s0[tid] = x[b * IN_DIM + tid];
        s0[HIDDEN + tid] = emb[company_idx[b] * EMB_DIM + tid];
    }
    __syncthreads();

    // input layer: 64 -> 256
    layer<IN_DIM>(W_in, b_in, s0, s1, j, sub);
    __syncthreads();
    // GAT layers (uniform-node collapse): 256 -> 256
    layer<HIDDEN>(gat_W,                     gat_b,       s1, s0, j, sub);
    __syncthreads();
    layer<HIDDEN>(gat_W + 1 * HIDDEN*HIDDEN, gat_b + 256, s0, s1, j, sub);
    __syncthreads();
    layer<HIDDEN>(gat_W + 2 * HIDDEN*HIDDEN, gat_b + 512, s1, s0, j, sub);
    __syncthreads();
    // fuse: 320 -> 256  (s0 = [gat2 out | emb])
    layer<FUSE_IN>(W_fuse, b_fuse, s0, s1, j, sub);
    __syncthreads();

    // p1 (outputs 0..127) and d1 (outputs 128..255), both read s1 -> s0
    if (j < 128) {
        layer<HIDDEN>(W_p1, b_p1, s1, s0, j, sub);
    } else {
        float r = qdot<HIDDEN>(W_d1 + (j - 128) * HIDDEN, s1, sub);
        if (sub == 0) s0[j] = fmaxf(r + b_d1[j - 128], 0.f);
    }
    __syncthreads();

    // p2 (s0[0:128] -> s1[0:64]) and d2 (s0[128:256] -> s1[64:128])
    if (warp < 16) {
        if (j < 64) {
            float r = qdot<128>(W_p2 + j * 128, s0, sub);
            if (sub == 0) s1[j] = fmaxf(r + b_p2[j], 0.f);
        } else {
            float r = qdot<128>(W_d2 + (j - 64) * 128, s0 + 128, sub);
            if (sub == 0) s1[j] = fmaxf(r + b_d2[j - 64], 0.f);
        }
    }
    __syncthreads();

    // heads: warp 0 -> price, warp 1 -> direction
    if (warp == 0) {
        float2 wv = reinterpret_cast<const float2*>(W_p3)[lane];
        float2 vv = reinterpret_cast<const float2*>(s1)[lane];
        float r = fmaf(wv.x, vv.x, wv.y * vv.y);
#pragma unroll
        for (int o = 16; o; o >>= 1) r += __shfl_xor_sync(0xffffffffu, r, o);
        if (lane == 0) out[b] = r + b_p3[0];
    } else if (warp == 1) {
        float2 wv = reinterpret_cast<const float2*>(W_d3)[lane];
        float2 vv = reinterpret_cast<const float2*>(s1 + 64)[lane];
        float r = fmaf(wv.x, vv.x, wv.y * vv.y);
#pragma unroll
        for (int o = 16; o; o >>= 1) r += __shfl_xor_sync(0xffffffffu, r, o);
        if (lane == 0) out[64 + b] = 1.f / (1.f + expf(-(r + b_d3[0])));
    }
}

extern "C" void kernel_launch(void* const* d_in, const int* in_sizes, int n_in,
                              void* d_out, int out_size) {
    const float* x        = (const float*)d_in[0];
    const int*   ci       = (const int*)  d_in[1];
    const float* W_in     = (const float*)d_in[4];
    const float* b_in     = (const float*)d_in[5];
    const float* gat_W    = (const float*)d_in[6];
    const float* gat_b    = (const float*)d_in[11];
    const float* emb      = (const float*)d_in[12];
    const float* W_fuse   = (const float*)d_in[13];
    const float* b_fuse   = (const float*)d_in[14];
    const float* W_p1     = (const float*)d_in[15];
    const float* b_p1     = (const float*)d_in[16];
    const float* W_p2     = (const float*)d_in[17];
    const float* b_p2     = (const float*)d_in[18];
    const float* W_p3     = (const float*)d_in[19];
    const float* b_p3     = (const float*)d_in[20];
    const float* W_d1     = (const float*)d_in[21];
    const float* b_d1     = (const float*)d_in[22];
    const float* W_d2     = (const float*)d_in[23];
    const float* b_d2     = (const float*)d_in[24];
    const float* W_d3     = (const float*)d_in[25];
    const float* b_d3     = (const float*)d_in[26];

    const int B = in_sizes[0] / IN_DIM;  // 64

    gat_collapse_kernel<<<B, 1024>>>(
        x, ci, W_in, b_in, gat_W, gat_b, emb, W_fuse, b_fuse,
        W_p1, b_p1, W_p2, b_p2, W_p3, b_p3,
        W_d1, b_d1, W_d2, b_d2, W_d3, b_d3,
        (float*)d_out, B);
}

// round 5
// speedup vs baseline: 1.9928x; 1.5774x over previous
#include <cuda_runtime.h>
#include <math.h>
#include <stdint.h>

// EnhancedFinancialGAT collapse: initial node features are uniform over nodes,
// so GAT attention (softmax, weights sum to 1) aggregates identical messages:
// each GAT layer == relu(W @ g + b). Whole net = per-item MLP chain.
//
// R4 -> R5: register-path LDG gave MLP~2 (regs=32 both rounds) -> latency
// serialization. Switch to cp.async.bulk (UBLKCP) weight streaming through
// double-buffered smem tiles; compute reads smem (29cyc). 23 tiles total.

#define IN_DIM 64
#define NTILES 23
#define BUF_BYTES (80 * 1024)
#define BUF_FLOATS (BUF_BYTES / 4)

struct Tile {
    uint8_t  wi;    // weight/bias pointer index
    uint8_t  c4;    // float4 per row
    uint8_t  vin;   // 0=s0, 1=s1, 2=s0+128
    uint8_t  vout;  // 0=s0, 1=s1, 2=s2
    uint16_t row0;  // row offset within weight matrix (and bias)
    uint16_t rows;  // rows in this tile (64 or 256)
    uint16_t voff;  // output offset
};

__device__ __constant__ Tile g_tiles[NTILES] = {
    // W_in: 256x64, s0 -> s1
    {0, 16, 0, 1, 0, 256, 0},
    // gat0: 256x256, s1 -> s0
    {1, 64, 1, 0,   0, 64,   0}, {1, 64, 1, 0,  64, 64,  64},
    {1, 64, 1, 0, 128, 64, 128}, {1, 64, 1, 0, 192, 64, 192},
    // gat1: s0 -> s1
    {2, 64, 0, 1,   0, 64,   0}, {2, 64, 0, 1,  64, 64,  64},
    {2, 64, 0, 1, 128, 64, 128}, {2, 64, 0, 1, 192, 64, 192},
    // gat2: s1 -> s0
    {3, 64, 1, 0,   0, 64,   0}, {3, 64, 1, 0,  64, 64,  64},
    {3, 64, 1, 0, 128, 64, 128}, {3, 64, 1, 0, 192, 64, 192},
    // fuse: 256x320, s0(+emb) -> s1
    {4, 80, 0, 1,   0, 64,   0}, {4, 80, 0, 1,  64, 64,  64},
    {4, 80, 0, 1, 128, 64, 128}, {4, 80, 0, 1, 192, 64, 192},
    // p1: 128x256, s1 -> s0[0:128]
    {5, 64, 1, 0, 0, 64, 0}, {5, 64, 1, 0, 64, 64, 64},
    // d1: 128x256, s1 -> s0[128:256]
    {6, 64, 1, 0, 0, 64, 128}, {6, 64, 1, 0, 64, 64, 192},
    // p2: 64x128, s0[0:128] -> s2[0:64]
    {7, 32, 0, 2, 0, 64, 0},
    // d2: 64x128, s0[128:256] -> s2[64:128]
    {8, 32, 2, 2, 0, 64, 64},
};

__device__ __forceinline__ uint32_t smem_u32(const void* p) {
    uint32_t a;
    asm("{ .reg .u64 t; cvta.to.shared.u64 t, %1; cvt.u32.u64 %0, t; }"
        : "=r"(a) : "l"(p));
    return a;
}

__device__ __forceinline__ void mbar_init(uint32_t a, uint32_t cnt) {
    asm volatile("mbarrier.init.shared.b64 [%0], %1;" :: "r"(a), "r"(cnt) : "memory");
}
__device__ __forceinline__ void mbar_expect_tx(uint32_t a, uint32_t bytes) {
    asm volatile("mbarrier.arrive.expect_tx.shared.b64 _, [%0], %1;"
                 :: "r"(a), "r"(bytes) : "memory");
}
__device__ __forceinline__ void bulk_g2s(uint32_t dst, const void* src,
                                         uint32_t bytes, uint32_t mbar) {
    asm volatile(
        "cp.async.bulk.shared::cluster.global.mbarrier::complete_tx::bytes "
        "[%0], [%1], %2, [%3];"
        :: "r"(dst), "l"(src), "r"(bytes), "r"(mbar) : "memory");
}
__device__ __forceinline__ void mbar_wait(uint32_t a, uint32_t parity) {
    uint32_t done;
    asm volatile(
        "{\n\t.reg .pred p;\n\t"
        "mbarrier.try_wait.parity.acquire.cta.shared::cta.b64 p, [%1], %2;\n\t"
        "selp.b32 %0, 1, 0, p;\n\t}"
        : "=r"(done) : "r"(a), "r"(parity) : "memory");
    if (!done) {
        asm volatile(
            "{\n\t.reg .pred P1;\n\t"
            "W_%=:\n\t"
            "mbarrier.try_wait.parity.acquire.cta.shared::cta.b64 P1, [%0], %1, 0x989680;\n\t"
            "@P1 bra.uni D_%=;\n\t"
            "bra.uni W_%=;\n\t"
            "D_%=:\n\t}"
            :: "r"(a), "r"(parity) : "memory");
    }
}

extern __shared__ __align__(16) float smem_dyn[];

__global__ __launch_bounds__(1024)
void gat_pipe_kernel(
    const float* __restrict__ x,            // [64,64]
    const int*   __restrict__ company_idx,  // [64]
    const float* __restrict__ W_in,  const float* __restrict__ b_in,
    const float* __restrict__ gat_W, const float* __restrict__ gat_b,
    const float* __restrict__ emb,
    const float* __restrict__ W_fuse, const float* __restrict__ b_fuse,
    const float* __restrict__ W_p1, const float* __restrict__ b_p1,
    const float* __restrict__ W_p2, const float* __restrict__ b_p2,
    const float* __restrict__ W_p3, const float* __restrict__ b_p3,
    const float* __restrict__ W_d1, const float* __restrict__ b_d1,
    const float* __restrict__ W_d2, const float* __restrict__ b_d2,
    const float* __restrict__ W_d3, const float* __restrict__ b_d3,
    float* __restrict__ out)
{
    float* buf0 = smem_dyn;
    float* buf1 = smem_dyn + BUF_FLOATS;
    float* s0   = smem_dyn + 2 * BUF_FLOATS;   // 320 floats (fuse input incl emb)
    float* s1   = s0 + 320;                    // 256
    float* s2   = s1 + 256;                    // 128
    uint64_t* mbar64 = (uint64_t*)(s2 + 128);  // 2 mbarriers

    const int tid = threadIdx.x;
    const int b   = blockIdx.x;

    const float* wp[9] = {W_in, gat_W, gat_W + 65536, gat_W + 131072,
                          W_fuse, W_p1, W_d1, W_p2, W_d2};
    const float* bp[9] = {b_in, gat_b, gat_b + 256, gat_b + 512,
                          b_fuse, b_p1, b_d1, b_p2, b_d2};
    float* vin_tab[3]  = {s0, s1, s0 + 128};
    float* vout_tab[3] = {s0, s1, s2};

    const uint32_t mb0 = smem_u32(mbar64);
    const uint32_t mb1 = mb0 + 8;
    const uint32_t bufa0 = smem_u32(buf0);
    const uint32_t bufa1 = smem_u32(buf1);

    if (tid == 0) { mbar_init(mb0, 1); mbar_init(mb1, 1); }
    // initial activations: x row + emb row
    if (tid < IN_DIM) {
        s0[tid] = x[b * IN_DIM + tid];
        s0[256 + tid] = emb[company_idx[b] * IN_DIM + tid];
    }
    __syncthreads();

    // kick tile 0
    if (tid == 0) {
        Tile t0 = g_tiles[0];
        uint32_t bytes = (uint32_t)t0.rows * t0.c4 * 16;
        mbar_expect_tx(mb0, bytes);
        bulk_g2s(bufa0, wp[t0.wi] + (uint32_t)t0.row0 * t0.c4 * 4, bytes, mb0);
    }

    for (int t = 0; t < NTILES; t++) {
        // prefetch tile t+1 into the other buffer (freed by tile t-1's sync)
        if (tid == 0 && t + 1 < NTILES) {
            Tile tn = g_tiles[t + 1];
            uint32_t bytes = (uint32_t)tn.rows * tn.c4 * 16;
            uint32_t mb = ((t + 1) & 1) ? mb1 : mb0;
            uint32_t dst = ((t + 1) & 1) ? bufa1 : bufa0;
            mbar_expect_tx(mb, bytes);
            bulk_g2s(dst, wp[tn.wi] + (uint32_t)tn.row0 * tn.c4 * 4, bytes, mb);
        }

        Tile ti = g_tiles[t];
        mbar_wait((t & 1) ? mb1 : mb0, (t >> 1) & 1);

        const int rows = ti.rows;          // 64 or 256
        const int L    = 1024 / rows;      // 16 or 4
        const int row  = tid / L;
        const int l    = tid - row * L;
        const int c4   = ti.c4;

        float bias = 0.f;
        if (l == 0) bias = __ldg(bp[ti.wi] + ti.row0 + row);

        const float4* w4 = reinterpret_cast<const float4*>((t & 1) ? buf1 : buf0)
                           + row * c4;
        const float4* v4 = reinterpret_cast<const float4*>(vin_tab[ti.vin]);

        float a0 = 0.f, a1 = 0.f, a2 = 0.f, a3 = 0.f;
        for (int i = l; i < c4; i += L) {
            float4 a = w4[i];
            float4 v = v4[i];
            a0 = fmaf(a.x, v.x, a0);
            a1 = fmaf(a.y, v.y, a1);
            a2 = fmaf(a.z, v.z, a2);
            a3 = fmaf(a.w, v.w, a3);
        }
        float r = (a0 + a1) + (a2 + a3);
        for (int o = L >> 1; o; o >>= 1) r += __shfl_xor_sync(0xffffffffu, r, o);
        if (l == 0) vout_tab[ti.vout][ti.voff + row] = fmaxf(r + bias, 0.f);

        __syncthreads();
    }

    // heads (s2 ready): warp0 -> price, warp1 -> direction
    if (tid < 32) {
        float2 wv = reinterpret_cast<const float2*>(W_p3)[tid];
        float2 vv = reinterpret_cast<const float2*>(s2)[tid];
        float r = fmaf(wv.x, vv.x, wv.y * vv.y);
#pragma unroll
        for (int o = 16; o; o >>= 1) r += __shfl_xor_sync(0xffffffffu, r, o);
        if (tid == 0) out[b] = r + b_p3[0];
    } else if (tid < 64) {
        int lane = tid - 32;
        float2 wv = reinterpret_cast<const float2*>(W_d3)[lane];
        float2 vv = reinterpret_cast<const float2*>(s2 + 64)[lane];
        float r = fmaf(wv.x, vv.x, wv.y * vv.y);
#pragma unroll
        for (int o = 16; o; o >>= 1) r += __shfl_xor_sync(0xffffffffu, r, o);
        if (lane == 0) out[64 + b] = 1.f / (1.f + expf(-(r + b_d3[0])));
    }
}

extern "C" void kernel_launch(void* const* d_in, const int* in_sizes, int n_in,
                              void* d_out, int out_size) {
    const float* x      = (const float*)d_in[0];
    const int*   ci     = (const int*)  d_in[1];
    const float* W_in   = (const float*)d_in[4];
    const float* b_in   = (const float*)d_in[5];
    const float* gat_W  = (const float*)d_in[6];
    const float* gat_b  = (const float*)d_in[11];
    const float* emb    = (const float*)d_in[12];
    const float* W_fuse = (const float*)d_in[13];
    const float* b_fuse = (const float*)d_in[14];
    const float* W_p1   = (const float*)d_in[15];
    const float* b_p1   = (const float*)d_in[16];
    const float* W_p2   = (const float*)d_in[17];
    const float* b_p2   = (const float*)d_in[18];
    const float* W_p3   = (const float*)d_in[19];
    const float* b_p3   = (const float*)d_in[20];
    const float* W_d1   = (const float*)d_in[21];
    const float* b_d1   = (const float*)d_in[22];
    const float* W_d2   = (const float*)d_in[23];
    const float* b_d2   = (const float*)d_in[24];
    const float* W_d3   = (const float*)d_in[25];
    const float* b_d3   = (const float*)d_in[26];

    const int B = in_sizes[0] / IN_DIM;  // 64

    // dynamic smem: 2 weight buffers + activations + mbarriers
    static int smem_bytes = 2 * BUF_BYTES + (320 + 256 + 128) * 4 + 16;
    cudaFuncSetAttribute(gat_pipe_kernel,
                         cudaFuncAttributeMaxDynamicSharedMemorySize, smem_bytes);

    gat_pipe_kernel<<<B, 1024, smem_bytes>>>(
        x, ci, W_in, b_in, gat_W, gat_b, emb, W_fuse, b_fuse,
        W_p1, b_p1, W_p2, b_p2, W_p3, b_p3,
        W_d1, b_d1, W_d2, b_d2, W_d3, b_d3,
        (float*)d_out);
}